// round 13
// baseline (speedup 1.0000x reference)
#include <cuda_runtime.h>
#include <cuda_bf16.h>
#include <math.h>
#include <cstdint>

// Problem dims
static constexpr int BATCH = 16;
static constexpr int DIMD  = 512;
static constexpr int NN    = 2048;
static constexpr int NSAMP = 15;
static constexpr int CSPLIT = 16;     // colsum row splits

// ---------------- scratch (device globals; no allocations allowed) ----------
__device__ float g_scores[(size_t)BATCH * NN * NN];   // 268 MB
__device__ float g_rowVal[BATCH * NN];
__device__ int   g_rowArg[BATCH * NN];
__device__ float g_colsum[BATCH * NN];
__device__ float g_colpart[(size_t)CSPLIT * BATCH * NN];
__device__ int   g_matchR[BATCH * NSAMP];
__device__ int   g_matchC[BATCH * NSAMP];

// bf16 split operands, K-major: [B][N][D]
__device__ __nv_bfloat16 g_Ah[(size_t)BATCH * NN * DIMD];
__device__ __nv_bfloat16 g_Al[(size_t)BATCH * NN * DIMD];
__device__ __nv_bfloat16 g_Bh[(size_t)BATCH * NN * DIMD];
__device__ __nv_bfloat16 g_Bl[(size_t)BATCH * NN * DIMD];

// ======================= PTX helpers (baseline PTX only) ====================
__device__ __forceinline__ uint32_t smem_u32(const void* p) {
    uint32_t a;
    asm("{ .reg .u64 t; cvta.to.shared.u64 t, %1; cvt.u32.u64 %0, t; }"
        : "=r"(a) : "l"(p));
    return a;
}
__device__ __forceinline__ void cp16(uint32_t dst, const void* src) {
    asm volatile("cp.async.cg.shared.global [%0], [%1], 16;" :: "r"(dst), "l"(src));
}
#define CP_COMMIT() asm volatile("cp.async.commit_group;" ::: "memory")
#define CP_WAIT(n)  asm volatile("cp.async.wait_group %0;" :: "n"(n) : "memory")

__device__ __forceinline__ void ldsm_x4(uint32_t& r0, uint32_t& r1,
                                        uint32_t& r2, uint32_t& r3, uint32_t addr) {
    asm volatile("ldmatrix.sync.aligned.m8n8.x4.shared.b16 {%0,%1,%2,%3}, [%4];"
                 : "=r"(r0), "=r"(r1), "=r"(r2), "=r"(r3) : "r"(addr));
}
__device__ __forceinline__ void mma16816(float* c, const uint32_t* a,
                                         uint32_t b0, uint32_t b1) {
    asm volatile("mma.sync.aligned.m16n8k16.row.col.f32.bf16.bf16.f32 "
                 "{%0,%1,%2,%3}, {%4,%5,%6,%7}, {%8,%9}, {%0,%1,%2,%3};"
                 : "+f"(c[0]), "+f"(c[1]), "+f"(c[2]), "+f"(c[3])
                 : "r"(a[0]), "r"(a[1]), "r"(a[2]), "r"(a[3]), "r"(b0), "r"(b1));
}

// ============ Kernel 0: transpose + bf16 split  [B,D,N] -> [B,N,D] hi/lo ====
// Fused for both embeddings: blockIdx.z in [0, 2*BATCH); z&1 selects tensor.
__global__ __launch_bounds__(256) void convert_kernel(
    const float* __restrict__ EA, const float* __restrict__ EB,
    __nv_bfloat16* __restrict__ OAh, __nv_bfloat16* __restrict__ OAl,
    __nv_bfloat16* __restrict__ OBh, __nv_bfloat16* __restrict__ OBl)
{
    __shared__ float tile[32][33];
    int z = blockIdx.z;
    int b = z >> 1, sel = z & 1;
    const float* E = sel ? EB : EA;
    __nv_bfloat16* Oh = sel ? OBh : OAh;
    __nv_bfloat16* Ol = sel ? OBl : OAl;

    int d0 = blockIdx.y * 32, n0 = blockIdx.x * 32;
    int tx = threadIdx.x & 31, ty = threadIdx.x >> 5;     // 32 x 8
    const float* Eb = E + (size_t)b * DIMD * NN;
#pragma unroll
    for (int i = 0; i < 4; i++) {
        int d = d0 + ty + i * 8;
        tile[ty + i * 8][tx] = Eb[(size_t)d * NN + n0 + tx];
    }
    __syncthreads();
    __nv_bfloat16* OhB = Oh + (size_t)b * NN * DIMD;
    __nv_bfloat16* OlB = Ol + (size_t)b * NN * DIMD;
#pragma unroll
    for (int i = 0; i < 4; i++) {
        int n = n0 + ty + i * 8;
        int d = d0 + tx;
        float v = tile[tx][ty + i * 8];
        __nv_bfloat16 hi = __float2bfloat16_rn(v);
        __nv_bfloat16 lo = __float2bfloat16_rn(v - __bfloat162float(hi));
        OhB[(size_t)n * DIMD + d] = hi;
        OlB[(size_t)n * DIMD + d] = lo;
    }
}

// ============ Kernel 1: HMMA bf16-split GEMM -> fp32 logits =================
// CTA tile 128x128, BK=32, 256 threads (8 warps, 4(m) x 2(n), warp 32x64).
// 3-stage cp.async pipeline, ONE __syncthreads per chunk.
static constexpr int BKC   = 32;                 // K per chunk
static constexpr int NKC   = DIMD / BKC;         // 16 chunks
static constexpr int STG   = 32768;              // 4 tiles x 8KB per stage
static constexpr int NSTG  = 3;
static constexpr int SM_GEMM_TOTAL = NSTG * STG; // 96 KB

// tile row = 64 bytes (32 bf16) = 4 x 16B chunks; swizzle chunk ^= (row>>1)&3
__device__ __forceinline__ uint32_t sw_off(int row, int c) {
    return (uint32_t)(row * 64 + ((c ^ ((row >> 1) & 3)) << 4));
}

__device__ __forceinline__ void load_stage(
    uint32_t stage_base, const __nv_bfloat16* Ahb, const __nv_bfloat16* Alb,
    const __nv_bfloat16* Bhb, const __nv_bfloat16* Blb, int k0, int tid)
{
    int t = tid >> 6;                 // 0..3 : which tile
    int sub = tid & 63;
    const __nv_bfloat16* base = (t == 0) ? Ahb : (t == 1) ? Alb : (t == 2) ? Bhb : Blb;
    uint32_t tbase = stage_base + t * 8192;
#pragma unroll
    for (int j = 0; j < 8; j++) {
        int ci = sub + j * 64;        // 0..511
        int row = ci >> 2, c = ci & 3;
        cp16(tbase + sw_off(row, c), base + (size_t)row * DIMD + k0 + c * 8);
    }
}

__global__ __launch_bounds__(256) void gemm_hmma_kernel()
{
    extern __shared__ char smem[];
    uint32_t sm0 = smem_u32(smem);
    int tid = threadIdx.x;
    int wid = tid >> 5, lane = tid & 31;
    int wm = wid & 3;                  // 0..3
    int wn = wid >> 2;                 // 0..1
    int b  = blockIdx.z;
    int s0 = blockIdx.y * 128;
    int t0 = blockIdx.x * 128;

    const __nv_bfloat16* Ahb = g_Ah + ((size_t)b * NN + s0) * DIMD;
    const __nv_bfloat16* Alb = g_Al + ((size_t)b * NN + s0) * DIMD;
    const __nv_bfloat16* Bhb = g_Bh + ((size_t)b * NN + t0) * DIMD;
    const __nv_bfloat16* Blb = g_Bl + ((size_t)b * NN + t0) * DIMD;

    float acc[2][8][4];
#pragma unroll
    for (int i = 0; i < 2; i++)
#pragma unroll
        for (int j = 0; j < 8; j++)
#pragma unroll
            for (int k = 0; k < 4; k++) acc[i][j][k] = 0.f;

    // prologue: stages 0 and 1 in flight
    load_stage(sm0, Ahb, Alb, Bhb, Blb, 0, tid);
    CP_COMMIT();
    load_stage(sm0 + STG, Ahb, Alb, Bhb, Blb, BKC, tid);
    CP_COMMIT();

    int stage = 0;
    for (int kc = 0; kc < NKC; kc++) {
        // invariant: commits so far = kc + 2; <=1 outstanding => group kc arrived
        CP_WAIT(1);
        __syncthreads();   // data visible to all warps; prior compute on the
                           // stage we are about to overwrite is finished

        // issue load for stage kc+2 (always commit, empty group at tail)
        if (kc + 2 < NKC) {
            int ns = stage + 2; if (ns >= NSTG) ns -= NSTG;
            load_stage(sm0 + ns * STG, Ahb, Alb, Bhb, Blb, (kc + 2) * BKC, tid);
        }
        CP_COMMIT();

        uint32_t sbase = sm0 + stage * STG;
#pragma unroll
        for (int h = 0; h < 2; h++) {
            uint32_t ah[2][4], al[2][4];
            int lr = lane & 15, lc = h * 2 + (lane >> 4);
#pragma unroll
            for (int f = 0; f < 2; f++) {
                int r = wm * 32 + f * 16 + lr;
                uint32_t off = sw_off(r, lc);
                ldsm_x4(ah[f][0], ah[f][1], ah[f][2], ah[f][3], sbase + off);
                ldsm_x4(al[f][0], al[f][1], al[f][2], al[f][3], sbase + 8192 + off);
            }
#pragma unroll
            for (int g = 0; g < 4; g++) {
                int r = wn * 64 + g * 16 + lr;
                uint32_t off = sw_off(r, lc);
                uint32_t bh[4], bl[4];
                ldsm_x4(bh[0], bh[1], bh[2], bh[3], sbase + 16384 + off);
                ldsm_x4(bl[0], bl[1], bl[2], bl[3], sbase + 24576 + off);
#pragma unroll
                for (int f = 0; f < 2; f++) {
                    // interleave the two target accumulators (RAW distance 2)
                    mma16816(acc[f][2 * g],     ah[f], bh[0], bh[2]);
                    mma16816(acc[f][2 * g + 1], ah[f], bh[1], bh[3]);
                    mma16816(acc[f][2 * g],     al[f], bh[0], bh[2]);
                    mma16816(acc[f][2 * g + 1], al[f], bh[1], bh[3]);
                    mma16816(acc[f][2 * g],     ah[f], bl[0], bl[2]);
                    mma16816(acc[f][2 * g + 1], ah[f], bl[1], bl[3]);
                }
            }
        }
        stage++; if (stage >= NSTG) stage -= NSTG;
    }

    // Epilogue: C frag m16n8: (c0,c1)->row lane/4, cols 2*(lane%4); (c2,c3)->row+8
    const float scale = 0.044194173824159216f;   // 1/sqrt(512)
    float* Ob = g_scores + (size_t)b * NN * NN;
    int rbase = s0 + wm * 32 + (lane >> 2);
    int cbase = t0 + wn * 64 + 2 * (lane & 3);
#pragma unroll
    for (int f = 0; f < 2; f++) {
#pragma unroll
        for (int n = 0; n < 8; n++) {
            int r = rbase + f * 16;
            int cg = cbase + n * 8;
            float2 v0 = make_float2(acc[f][n][0] * scale, acc[f][n][1] * scale);
            float2 v1 = make_float2(acc[f][n][2] * scale, acc[f][n][3] * scale);
            *reinterpret_cast<float2*>(&Ob[(size_t)r * NN + cg])       = v0;
            *reinterpret_cast<float2*>(&Ob[(size_t)(r + 8) * NN + cg]) = v1;
        }
    }
}

// ---------------- Kernel 2: single-pass register-resident softmax -----------
__global__ __launch_bounds__(256) void softmax_kernel()
{
    int row = blockIdx.x;                       // 0 .. B*N-1
    float* p = g_scores + (size_t)row * NN;
    int tid = threadIdx.x;
    int lane = tid & 31, warp = tid >> 5;
    __shared__ float wred[8];
    __shared__ int   wredi[8];

    float4 v0 = reinterpret_cast<const float4*>(p)[tid * 2];
    float4 v1 = reinterpret_cast<const float4*>(p)[tid * 2 + 1];
    float vals[8] = {v0.x, v0.y, v0.z, v0.w, v1.x, v1.y, v1.z, v1.w};

    float m = vals[0];
#pragma unroll
    for (int j = 1; j < 8; j++) m = fmaxf(m, vals[j]);
#pragma unroll
    for (int s = 16; s > 0; s >>= 1) m = fmaxf(m, __shfl_xor_sync(~0u, m, s));
    if (lane == 0) wred[warp] = m;
    __syncthreads();
    if (warp == 0) {
        float t = (lane < 8) ? wred[lane] : -3.4e38f;
#pragma unroll
        for (int s = 4; s > 0; s >>= 1) t = fmaxf(t, __shfl_xor_sync(~0u, t, s));
        if (lane == 0) wred[0] = t;
    }
    __syncthreads();
    float M = wred[0];
    __syncthreads();

    float ev[8];
    float sum = 0.f;
#pragma unroll
    for (int j = 0; j < 8; j++) { ev[j] = __expf(vals[j] - M); sum += ev[j]; }
#pragma unroll
    for (int s = 16; s > 0; s >>= 1) sum += __shfl_xor_sync(~0u, sum, s);
    if (lane == 0) wred[warp] = sum;
    __syncthreads();
    if (warp == 0) {
        float t = (lane < 8) ? wred[lane] : 0.f;
#pragma unroll
        for (int s = 4; s > 0; s >>= 1) t += __shfl_xor_sync(~0u, t, s);
        if (lane == 0) wred[0] = t;
    }
    __syncthreads();
    float inv = 1.0f / wred[0];
    __syncthreads();

    float sv[8];
#pragma unroll
    for (int j = 0; j < 8; j++) sv[j] = ev[j] * inv;
    reinterpret_cast<float4*>(p)[tid * 2]     = make_float4(sv[0], sv[1], sv[2], sv[3]);
    reinterpret_cast<float4*>(p)[tid * 2 + 1] = make_float4(sv[4], sv[5], sv[6], sv[7]);

    float mv = sv[0]; int mc = tid * 8;
#pragma unroll
    for (int j = 1; j < 8; j++)
        if (sv[j] > mv) { mv = sv[j]; mc = tid * 8 + j; }
#pragma unroll
    for (int s = 16; s > 0; s >>= 1) {
        float ov = __shfl_xor_sync(~0u, mv, s);
        int   oc = __shfl_xor_sync(~0u, mc, s);
        if (ov > mv || (ov == mv && oc < mc)) { mv = ov; mc = oc; }
    }
    if (lane == 0) { wred[warp] = mv; wredi[warp] = mc; }
    __syncthreads();
    if (warp == 0) {
        float t = (lane < 8) ? wred[lane] : -1.f;
        int   c = (lane < 8) ? wredi[lane] : 0;
#pragma unroll
        for (int s = 4; s > 0; s >>= 1) {
            float ov = __shfl_xor_sync(~0u, t, s);
            int   oc = __shfl_xor_sync(~0u, c, s);
            if (ov > t || (ov == t && oc < c)) { t = ov; c = oc; }
        }
        if (lane == 0) { g_rowVal[row] = t; g_rowArg[row] = c; }
    }
}

// ---------------- Kernel 3a: split-K column partial sums --------------------
__global__ __launch_bounds__(256) void colsum_part_kernel()
{
    int b = blockIdx.y;
    int z = blockIdx.z;
    int c4 = blockIdx.x * 256 + threadIdx.x;           // float4 index, 0..511
    const float* sc = g_scores + (size_t)b * NN * NN + z * 128 * NN;
    float4 s = make_float4(0.f, 0.f, 0.f, 0.f);
    for (int r = 0; r < 128; r++) {
        float4 v = reinterpret_cast<const float4*>(sc + (size_t)r * NN)[c4];
        s.x += v.x; s.y += v.y; s.z += v.z; s.w += v.w;
    }
    reinterpret_cast<float4*>(g_colpart + ((size_t)z * BATCH + b) * NN)[c4] = s;
}

// ---------------- Kernel 3b: reduce partials --------------------------------
__global__ __launch_bounds__(256) void colsum_reduce_kernel()
{
    int i = blockIdx.x * 256 + threadIdx.x;            // 0 .. BATCH*NN-1
    int b = i >> 11, c = i & (NN - 1);
    float s = 0.f;
    for (int z = 0; z < CSPLIT; z++)
        s += g_colpart[((size_t)z * BATCH + b) * NN + c];
    g_colsum[i] = s;
}

// ---------------- Kernel 4: greedy one-to-one matching (1024 threads) -------
static constexpr int MBLK = 1024;
__global__ __launch_bounds__(MBLK) void match_kernel()
{
    int b = blockIdx.x;
    int tid = threadIdx.x;
    __shared__ float rVal[NN];
    __shared__ int   rArg[NN];
    __shared__ unsigned char colDead[NN];
    __shared__ float redV[MBLK];
    __shared__ int   redI[MBLK];
    __shared__ int   list[256];
    __shared__ int   listCnt;
    __shared__ int   selC;

    for (int i = tid; i < NN; i += MBLK) {
        rVal[i] = g_rowVal[b * NN + i];
        rArg[i] = g_rowArg[b * NN + i];
        colDead[i] = 0;
    }
    __syncthreads();

    const float* sc = g_scores + (size_t)b * NN * NN;

    for (int it = 0; it < NSAMP; it++) {
        float bv = -1.f; int br = 0;
        for (int r = tid; r < NN; r += MBLK) {
            float v = rVal[r];
            if (v > bv) { bv = v; br = r; }
        }
        redV[tid] = bv; redI[tid] = br; __syncthreads();
        for (int s = MBLK / 2; s > 0; s >>= 1) {
            if (tid < s) {
                float v2 = redV[tid + s]; int r2 = redI[tid + s];
                if (v2 > redV[tid] || (v2 == redV[tid] && r2 < redI[tid])) {
                    redV[tid] = v2; redI[tid] = r2;
                }
            }
            __syncthreads();
        }
        if (tid == 0) {
            int r = redI[0];
            int c = rArg[r];
            g_matchR[b * NSAMP + it] = r;
            g_matchC[b * NSAMP + it] = c;
            rVal[r] = -1.f;
            colDead[c] = 1;
            selC = c;
            listCnt = 0;
        }
        __syncthreads();

        int c = selC;
        for (int r = tid; r < NN; r += MBLK) {
            if (rVal[r] >= 0.f && rArg[r] == c) {
                int pos = atomicAdd(&listCnt, 1);
                if (pos < 256) list[pos] = r;
            }
        }
        __syncthreads();
        int cnt = listCnt; if (cnt > 256) cnt = 256;
        for (int li = 0; li < cnt; li++) {
            int r = list[li];
            const float* rowp = sc + (size_t)r * NN;
            float mv = -1.f; int mc = 0;
            for (int cc = tid; cc < NN; cc += MBLK) {
                if (!colDead[cc]) {
                    float v = rowp[cc];
                    if (v > mv) { mv = v; mc = cc; }
                }
            }
            redV[tid] = mv; redI[tid] = mc; __syncthreads();
            for (int s = MBLK / 2; s > 0; s >>= 1) {
                if (tid < s) {
                    float v2 = redV[tid + s]; int c2 = redI[tid + s];
                    if (v2 > redV[tid] || (v2 == redV[tid] && c2 < redI[tid])) {
                        redV[tid] = v2; redI[tid] = c2;
                    }
                }
                __syncthreads();
            }
            if (tid == 0) { rVal[r] = redV[0]; rArg[r] = redI[0]; }
            __syncthreads();
        }
        __syncthreads();
    }
}

// ---------------- Kernel 5: gather + centroids + 3x3 Kabsch SVD + output ----
__global__ __launch_bounds__(128) void finalize_kernel(
    const float* __restrict__ src, const float* __restrict__ tgt,
    float* __restrict__ out, int out_size)
{
    int b = blockIdx.x, tid = threadIdx.x;
    __shared__ float rx[128], ry[128], rz[128];
    __shared__ float srcMean[3], corrMean[3];
    __shared__ float sp[NSAMP][3], tp[NSAMP][3];

    const float* sb = src + (size_t)b * NN * 3;
    const float* tb = tgt + (size_t)b * NN * 3;

    float sx = 0, sy = 0, sz = 0;
    for (int n = tid; n < NN; n += 128) {
        sx += sb[3 * n]; sy += sb[3 * n + 1]; sz += sb[3 * n + 2];
    }
    rx[tid] = sx; ry[tid] = sy; rz[tid] = sz; __syncthreads();
    for (int s = 64; s > 0; s >>= 1) {
        if (tid < s) { rx[tid] += rx[tid + s]; ry[tid] += ry[tid + s]; rz[tid] += rz[tid + s]; }
        __syncthreads();
    }
    if (tid == 0) {
        srcMean[0] = rx[0] / NN; srcMean[1] = ry[0] / NN; srcMean[2] = rz[0] / NN;
    }
    __syncthreads();

    sx = sy = sz = 0;
    for (int n = tid; n < NN; n += 128) {
        float w = g_colsum[b * NN + n];
        sx += tb[3 * n] * w; sy += tb[3 * n + 1] * w; sz += tb[3 * n + 2] * w;
    }
    rx[tid] = sx; ry[tid] = sy; rz[tid] = sz; __syncthreads();
    for (int s = 64; s > 0; s >>= 1) {
        if (tid < s) { rx[tid] += rx[tid + s]; ry[tid] += ry[tid + s]; rz[tid] += rz[tid + s]; }
        __syncthreads();
    }
    if (tid == 0) {
        corrMean[0] = rx[0] / NN; corrMean[1] = ry[0] / NN; corrMean[2] = rz[0] / NN;
    }

    if (tid < NSAMP) {
        int r = g_matchR[b * NSAMP + tid];
        int c = g_matchC[b * NSAMP + tid];
        sp[tid][0] = sb[3 * r]; sp[tid][1] = sb[3 * r + 1]; sp[tid][2] = sb[3 * r + 2];
        tp[tid][0] = tb[3 * c]; tp[tid][1] = tb[3 * c + 1]; tp[tid][2] = tb[3 * c + 2];
    }
    __syncthreads();

    if (tid == 0) {
        double ms[3] = {0, 0, 0}, mt[3] = {0, 0, 0};
        for (int s = 0; s < NSAMP; s++)
            for (int i = 0; i < 3; i++) { ms[i] += sp[s][i]; mt[i] += tp[s][i]; }
        for (int i = 0; i < 3; i++) { ms[i] /= NSAMP; mt[i] /= NSAMP; }

        double H[3][3] = {};
        for (int s = 0; s < NSAMP; s++)
            for (int i = 0; i < 3; i++)
                for (int j = 0; j < 3; j++)
                    H[i][j] += ((double)sp[s][i] - ms[i]) * ((double)tp[s][j] - mt[j]);

        double Sm[3][3];
        for (int i = 0; i < 3; i++)
            for (int j = 0; j < 3; j++) {
                double acc = 0;
                for (int k = 0; k < 3; k++) acc += H[k][i] * H[k][j];
                Sm[i][j] = acc;
            }
        double V[3][3] = {{1, 0, 0}, {0, 1, 0}, {0, 0, 1}};
        for (int sweep = 0; sweep < 12; sweep++) {
            for (int pi = 0; pi < 3; pi++) {
                for (int qi = pi + 1; qi < 3; qi++) {
                    double apq = Sm[pi][qi];
                    if (fabs(apq) < 1e-30) continue;
                    double app = Sm[pi][pi], aqq = Sm[qi][qi];
                    double theta = 0.5 * (aqq - app) / apq;
                    double tJ = ((theta >= 0) ? 1.0 : -1.0) /
                                (fabs(theta) + sqrt(theta * theta + 1.0));
                    double cJ = 1.0 / sqrt(tJ * tJ + 1.0);
                    double sJ = tJ * cJ;
                    for (int k = 0; k < 3; k++) {
                        double skp = Sm[k][pi], skq = Sm[k][qi];
                        Sm[k][pi] = cJ * skp - sJ * skq;
                        Sm[k][qi] = sJ * skp + cJ * skq;
                    }
                    for (int k = 0; k < 3; k++) {
                        double spk = Sm[pi][k], sqk = Sm[qi][k];
                        Sm[pi][k] = cJ * spk - sJ * sqk;
                        Sm[qi][k] = sJ * spk + cJ * sqk;
                    }
                    for (int k = 0; k < 3; k++) {
                        double vkp = V[k][pi], vkq = V[k][qi];
                        V[k][pi] = cJ * vkp - sJ * vkq;
                        V[k][qi] = sJ * vkp + cJ * vkq;
                    }
                }
            }
        }
        double lam[3] = {Sm[0][0], Sm[1][1], Sm[2][2]};
        int idx[3] = {0, 1, 2};
        for (int i = 0; i < 2; i++)
            for (int j = i + 1; j < 3; j++)
                if (lam[idx[j]] > lam[idx[i]]) { int t2 = idx[i]; idx[i] = idx[j]; idx[j] = t2; }
        double Vc[3][3], U[3][3];
        for (int k = 0; k < 3; k++) {
            int c = idx[k];
            double sig = sqrt(lam[c] > 0 ? lam[c] : 0);
            double invs = (sig > 1e-300) ? 1.0 / sig : 0.0;
            for (int i = 0; i < 3; i++) Vc[i][k] = V[i][c];
            for (int i = 0; i < 3; i++) {
                double acc = 0;
                for (int j = 0; j < 3; j++) acc += H[i][j] * Vc[j][k];
                U[i][k] = acc * invs;
            }
        }
        double R[3][3];
        for (int i = 0; i < 3; i++)
            for (int j = 0; j < 3; j++) {
                double acc = 0;
                for (int k = 0; k < 3; k++) acc += Vc[i][k] * U[j][k];
                R[i][j] = acc;
            }
        double det =
            R[0][0] * (R[1][1] * R[2][2] - R[1][2] * R[2][1]) -
            R[0][1] * (R[1][0] * R[2][2] - R[1][2] * R[2][0]) +
            R[0][2] * (R[1][0] * R[2][1] - R[1][1] * R[2][0]);
        if (det < 0) {
            for (int i = 0; i < 3; i++)
                for (int j = 0; j < 3; j++)
                    R[i][j] -= 2.0 * Vc[i][2] * U[j][2];
        }
        double tv[3];
        for (int i = 0; i < 3; i++) {
            double acc = 0;
            for (int j = 0; j < 3; j++) acc += R[i][j] * (double)srcMean[j];
            tv[i] = -acc + (double)corrMean[i];
        }
        for (int i = 0; i < 3; i++)
            for (int j = 0; j < 3; j++)
                out[b * 9 + i * 3 + j] = (float)R[i][j];
        if (out_size >= BATCH * 9 + BATCH * 3) {
            for (int i = 0; i < 3; i++)
                out[BATCH * 9 + b * 3 + i] = (float)tv[i];
        }
    }
}

// ---------------- launch ----------------
extern "C" void kernel_launch(void* const* d_in, const int* in_sizes, int n_in,
                              void* d_out, int out_size)
{
    const float* src_emb = (const float*)d_in[0];
    const float* tgt_emb = (const float*)d_in[1];
    const float* src     = (const float*)d_in[2];
    const float* tgt     = (const float*)d_in[3];
    float* out = (float*)d_out;

    cudaFuncSetAttribute(gemm_hmma_kernel,
                         cudaFuncAttributeMaxDynamicSharedMemorySize, SM_GEMM_TOTAL);

    __nv_bfloat16 *pAh, *pAl, *pBh, *pBl;
    cudaGetSymbolAddress((void**)&pAh, g_Ah);
    cudaGetSymbolAddress((void**)&pAl, g_Al);
    cudaGetSymbolAddress((void**)&pBh, g_Bh);
    cudaGetSymbolAddress((void**)&pBl, g_Bl);

    dim3 gConv(NN / 32, DIMD / 32, 2 * BATCH);
    convert_kernel<<<gConv, 256>>>(src_emb, tgt_emb, pAh, pAl, pBh, pBl);

    dim3 gGemm(NN / 128, NN / 128, BATCH);
    gemm_hmma_kernel<<<gGemm, 256, SM_GEMM_TOTAL>>>();

    softmax_kernel<<<BATCH * NN, 256>>>();

    dim3 gColP(2, BATCH, CSPLIT);
    colsum_part_kernel<<<gColP, 256>>>();
    colsum_reduce_kernel<<<(BATCH * NN) / 256, 256>>>();

    match_kernel<<<BATCH, MBLK>>>();

    finalize_kernel<<<BATCH, 128>>>(src, tgt, out, out_size);
}

// round 16
// speedup vs baseline: 1.0997x; 1.0997x over previous
#include <cuda_runtime.h>
#include <cuda_bf16.h>
#include <math.h>
#include <cstdint>

// Problem dims
static constexpr int BATCH = 16;
static constexpr int DIMD  = 512;
static constexpr int NN    = 2048;
static constexpr int NSAMP = 15;
static constexpr int CSPLIT = 16;     // colsum row splits
static constexpr int TTILES = NN / 128;  // 16 t-tiles (row-stats partials)

// ---------------- scratch (device globals; no allocations allowed) ----------
__device__ float g_scores[(size_t)BATCH * NN * NN];   // stores E = exp(logit)
__device__ float g_rowVal[BATCH * NN];                // max score per row
__device__ int   g_rowArg[BATCH * NN];
__device__ float g_inv[BATCH * NN];                   // 1 / rowsum(E)
__device__ float g_colsum[BATCH * NN];
__device__ float g_colpart[(size_t)CSPLIT * BATCH * NN];
__device__ float g_rsum_part[TTILES][BATCH * NN];
__device__ float g_rmax_part[TTILES][BATCH * NN];
__device__ int   g_rarg_part[TTILES][BATCH * NN];
__device__ int   g_matchR[BATCH * NSAMP];
__device__ int   g_matchC[BATCH * NSAMP];

// bf16 split operands, K-major: [B][N][D]
__device__ __nv_bfloat16 g_Ah[(size_t)BATCH * NN * DIMD];
__device__ __nv_bfloat16 g_Al[(size_t)BATCH * NN * DIMD];
__device__ __nv_bfloat16 g_Bh[(size_t)BATCH * NN * DIMD];
__device__ __nv_bfloat16 g_Bl[(size_t)BATCH * NN * DIMD];

// ======================= PTX helpers (baseline PTX only) ====================
__device__ __forceinline__ uint32_t smem_u32(const void* p) {
    uint32_t a;
    asm("{ .reg .u64 t; cvta.to.shared.u64 t, %1; cvt.u32.u64 %0, t; }"
        : "=r"(a) : "l"(p));
    return a;
}
__device__ __forceinline__ void cp16(uint32_t dst, const void* src) {
    asm volatile("cp.async.cg.shared.global [%0], [%1], 16;" :: "r"(dst), "l"(src));
}
#define CP_COMMIT() asm volatile("cp.async.commit_group;" ::: "memory")
#define CP_WAIT(n)  asm volatile("cp.async.wait_group %0;" :: "n"(n) : "memory")

__device__ __forceinline__ void ldsm_x4(uint32_t& r0, uint32_t& r1,
                                        uint32_t& r2, uint32_t& r3, uint32_t addr) {
    asm volatile("ldmatrix.sync.aligned.m8n8.x4.shared.b16 {%0,%1,%2,%3}, [%4];"
                 : "=r"(r0), "=r"(r1), "=r"(r2), "=r"(r3) : "r"(addr));
}
__device__ __forceinline__ void mma16816(float* c, const uint32_t* a,
                                         uint32_t b0, uint32_t b1) {
    asm volatile("mma.sync.aligned.m16n8k16.row.col.f32.bf16.bf16.f32 "
                 "{%0,%1,%2,%3}, {%4,%5,%6,%7}, {%8,%9}, {%0,%1,%2,%3};"
                 : "+f"(c[0]), "+f"(c[1]), "+f"(c[2]), "+f"(c[3])
                 : "r"(a[0]), "r"(a[1]), "r"(a[2]), "r"(a[3]), "r"(b0), "r"(b1));
}

// ============ Kernel 0: transpose + bf16 split  [B,D,N] -> [B,N,D] hi/lo ====
__global__ __launch_bounds__(256) void convert_kernel(
    const float* __restrict__ EA, const float* __restrict__ EB,
    __nv_bfloat16* __restrict__ OAh, __nv_bfloat16* __restrict__ OAl,
    __nv_bfloat16* __restrict__ OBh, __nv_bfloat16* __restrict__ OBl)
{
    __shared__ float tile[32][33];
    int z = blockIdx.z;
    int b = z >> 1, sel = z & 1;
    const float* E = sel ? EB : EA;
    __nv_bfloat16* Oh = sel ? OBh : OAh;
    __nv_bfloat16* Ol = sel ? OBl : OAl;

    int d0 = blockIdx.y * 32, n0 = blockIdx.x * 32;
    int tx = threadIdx.x & 31, ty = threadIdx.x >> 5;     // 32 x 8
    const float* Eb = E + (size_t)b * DIMD * NN;
#pragma unroll
    for (int i = 0; i < 4; i++) {
        int d = d0 + ty + i * 8;
        tile[ty + i * 8][tx] = Eb[(size_t)d * NN + n0 + tx];
    }
    __syncthreads();
    __nv_bfloat16* OhB = Oh + (size_t)b * NN * DIMD;
    __nv_bfloat16* OlB = Ol + (size_t)b * NN * DIMD;
#pragma unroll
    for (int i = 0; i < 4; i++) {
        int n = n0 + ty + i * 8;
        int d = d0 + tx;
        float v = tile[tx][ty + i * 8];
        __nv_bfloat16 hi = __float2bfloat16_rn(v);
        __nv_bfloat16 lo = __float2bfloat16_rn(v - __bfloat162float(hi));
        OhB[(size_t)n * DIMD + d] = hi;
        OlB[(size_t)n * DIMD + d] = lo;
    }
}

// ============ Kernel 1: HMMA bf16-split GEMM -> E = exp(logit) + row stats ==
static constexpr int BKC   = 32;                 // K per chunk
static constexpr int NKC   = DIMD / BKC;         // 16 chunks
static constexpr int STG   = 32768;              // 4 tiles x 8KB per stage
static constexpr int NSTG  = 3;
static constexpr int SM_GEMM_TOTAL = NSTG * STG; // 96 KB

__device__ __forceinline__ uint32_t sw_off(int row, int c) {
    return (uint32_t)(row * 64 + ((c ^ ((row >> 1) & 3)) << 4));
}

__device__ __forceinline__ void load_stage(
    uint32_t stage_base, const __nv_bfloat16* Ahb, const __nv_bfloat16* Alb,
    const __nv_bfloat16* Bhb, const __nv_bfloat16* Blb, int k0, int tid)
{
    int t = tid >> 6;                 // 0..3 : which tile
    int sub = tid & 63;
    const __nv_bfloat16* base = (t == 0) ? Ahb : (t == 1) ? Alb : (t == 2) ? Bhb : Blb;
    uint32_t tbase = stage_base + t * 8192;
#pragma unroll
    for (int j = 0; j < 8; j++) {
        int ci = sub + j * 64;        // 0..511
        int row = ci >> 2, c = ci & 3;
        cp16(tbase + sw_off(row, c), base + (size_t)row * DIMD + k0 + c * 8);
    }
}

__global__ __launch_bounds__(256) void gemm_hmma_kernel()
{
    extern __shared__ char smem[];
    uint32_t sm0 = smem_u32(smem);
    int tid = threadIdx.x;
    int wid = tid >> 5, lane = tid & 31;
    int wm = wid & 3;                  // 0..3
    int wn = wid >> 2;                 // 0..1
    int b  = blockIdx.z;
    int s0 = blockIdx.y * 128;
    int t0 = blockIdx.x * 128;

    const __nv_bfloat16* Ahb = g_Ah + ((size_t)b * NN + s0) * DIMD;
    const __nv_bfloat16* Alb = g_Al + ((size_t)b * NN + s0) * DIMD;
    const __nv_bfloat16* Bhb = g_Bh + ((size_t)b * NN + t0) * DIMD;
    const __nv_bfloat16* Blb = g_Bl + ((size_t)b * NN + t0) * DIMD;

    float acc[2][8][4];
#pragma unroll
    for (int i = 0; i < 2; i++)
#pragma unroll
        for (int j = 0; j < 8; j++)
#pragma unroll
            for (int k = 0; k < 4; k++) acc[i][j][k] = 0.f;

    // prologue: stages 0 and 1 in flight
    load_stage(sm0, Ahb, Alb, Bhb, Blb, 0, tid);
    CP_COMMIT();
    load_stage(sm0 + STG, Ahb, Alb, Bhb, Blb, BKC, tid);
    CP_COMMIT();

    int stage = 0;
    for (int kc = 0; kc < NKC; kc++) {
        CP_WAIT(1);
        __syncthreads();

        if (kc + 2 < NKC) {
            int ns = stage + 2; if (ns >= NSTG) ns -= NSTG;
            load_stage(sm0 + ns * STG, Ahb, Alb, Bhb, Blb, (kc + 2) * BKC, tid);
        }
        CP_COMMIT();

        uint32_t sbase = sm0 + stage * STG;
#pragma unroll
        for (int h = 0; h < 2; h++) {
            uint32_t ah[2][4], al[2][4];
            int lr16 = lane & 15, lc = h * 2 + (lane >> 4);
#pragma unroll
            for (int f = 0; f < 2; f++) {
                int r = wm * 32 + f * 16 + lr16;
                uint32_t off = sw_off(r, lc);
                ldsm_x4(ah[f][0], ah[f][1], ah[f][2], ah[f][3], sbase + off);
                ldsm_x4(al[f][0], al[f][1], al[f][2], al[f][3], sbase + 8192 + off);
            }
#pragma unroll
            for (int g = 0; g < 4; g++) {
                int r = wn * 64 + g * 16 + lr16;
                uint32_t off = sw_off(r, lc);
                uint32_t bh[4], bl[4];
                ldsm_x4(bh[0], bh[1], bh[2], bh[3], sbase + 16384 + off);
                ldsm_x4(bl[0], bl[1], bl[2], bl[3], sbase + 24576 + off);
#pragma unroll
                for (int f = 0; f < 2; f++) {
                    mma16816(acc[f][2 * g],     ah[f], bh[0], bh[2]);
                    mma16816(acc[f][2 * g + 1], ah[f], bh[1], bh[3]);
                    mma16816(acc[f][2 * g],     al[f], bh[0], bh[2]);
                    mma16816(acc[f][2 * g + 1], al[f], bh[1], bh[3]);
                    mma16816(acc[f][2 * g],     ah[f], bl[0], bl[2]);
                    mma16816(acc[f][2 * g + 1], ah[f], bl[1], bl[3]);
                }
            }
        }
        stage++; if (stage >= NSTG) stage -= NSTG;
    }

    // ---- Epilogue: E = exp(logit); store; per-row partial sum/max/argmax ----
    const float scale = 0.044194173824159216f;   // 1/sqrt(512)
#pragma unroll
    for (int f = 0; f < 2; f++)
#pragma unroll
        for (int n = 0; n < 8; n++)
#pragma unroll
            for (int k = 0; k < 4; k++)
                acc[f][n][k] = __expf(acc[f][n][k] * scale);

    float* Ob = g_scores + (size_t)b * NN * NN;
    int lr = lane >> 2, lq = lane & 3;
    int rbase = s0 + wm * 32 + lr;
    int cbase = t0 + wn * 64 + 2 * lq;
#pragma unroll
    for (int f = 0; f < 2; f++) {
#pragma unroll
        for (int n = 0; n < 8; n++) {
            int r = rbase + f * 16;
            int cg = cbase + n * 8;
            *reinterpret_cast<float2*>(&Ob[(size_t)r * NN + cg]) =
                make_float2(acc[f][n][0], acc[f][n][1]);
            *reinterpret_cast<float2*>(&Ob[(size_t)(r + 8) * NN + cg]) =
                make_float2(acc[f][n][2], acc[f][n][3]);
        }
    }

    // per-thread partials for 4 rows: (f, half)
    float qsum[4], qmax[4]; int qarg[4];
    int i4 = 0;
#pragma unroll
    for (int f = 0; f < 2; f++) {
#pragma unroll
        for (int half = 0; half < 2; half++) {
            float rs = 0.f, rm = -1.f; int ra = 0;
#pragma unroll
            for (int n = 0; n < 8; n++) {
#pragma unroll
                for (int j = 0; j < 2; j++) {
                    float v = acc[f][n][half * 2 + j];
                    rs += v;
                    if (v > rm) { rm = v; ra = cbase + n * 8 + j; }  // cols ascending
                }
            }
            // quad reduce (lanes sharing the same rows)
#pragma unroll
            for (int s2 = 1; s2 <= 2; s2 <<= 1) {
                rs += __shfl_xor_sync(~0u, rs, s2);
                float om = __shfl_xor_sync(~0u, rm, s2);
                int   oa = __shfl_xor_sync(~0u, ra, s2);
                if (om > rm || (om == rm && oa < ra)) { rm = om; ra = oa; }
            }
            qsum[i4] = rs; qmax[i4] = rm; qarg[i4] = ra; i4++;
        }
    }

    __syncthreads();   // stage smem no longer needed; reuse for stats
    float* ssum = reinterpret_cast<float*>(smem);       // [2][4][32]
    float* smax = ssum + 256;
    int*   sarg = reinterpret_cast<int*>(smax + 256);
    if (lq == 0) {
        i4 = 0;
#pragma unroll
        for (int f = 0; f < 2; f++)
#pragma unroll
            for (int half = 0; half < 2; half++) {
                int rrow = f * 16 + half * 8 + lr;               // 0..31
                int o = wn * 128 + wm * 32 + rrow;
                ssum[o] = qsum[i4]; smax[o] = qmax[i4]; sarg[o] = qarg[i4];
                i4++;
            }
    }
    __syncthreads();
    if (tid < 128) {
        int wmx = tid >> 5, r32 = tid & 31;
        int o0 = wmx * 32 + r32, o1 = 128 + o0;
        float s = ssum[o0] + ssum[o1];
        float m = smax[o0]; int a = sarg[o0];
        float m1 = smax[o1]; int a1 = sarg[o1];
        if (m1 > m || (m1 == m && a1 < a)) { m = m1; a = a1; }
        int grow = b * NN + s0 + wmx * 32 + r32;
        g_rsum_part[blockIdx.x][grow] = s;
        g_rmax_part[blockIdx.x][grow] = m;
        g_rarg_part[blockIdx.x][grow] = a;
    }
}

// ---------------- Kernel 2: reduce row stats -> inv, rowVal, rowArg ---------
__global__ __launch_bounds__(256) void stats_reduce_kernel()
{
    int i = blockIdx.x * 256 + threadIdx.x;    // 0 .. BATCH*NN-1
    float s = 0.f, mx = -1.f; int ag = 0;
#pragma unroll
    for (int z = 0; z < TTILES; z++) {         // ascending t -> tie keeps smallest col
        s += g_rsum_part[z][i];
        float m = g_rmax_part[z][i]; int a = g_rarg_part[z][i];
        if (m > mx || (m == mx && a < ag)) { mx = m; ag = a; }
    }
    float inv = 1.0f / s;
    g_inv[i] = inv;
    g_rowVal[i] = mx * inv;
    g_rowArg[i] = ag;
}

// ---------------- Kernel 3a: split-K column partial sums (of E * inv) -------
__global__ __launch_bounds__(256) void colsum_part_kernel()
{
    int b = blockIdx.y;
    int z = blockIdx.z;
    int c4 = blockIdx.x * 256 + threadIdx.x;           // float4 index, 0..511
    const float* sc = g_scores + (size_t)b * NN * NN + (size_t)z * 128 * NN;
    const float* ivp = g_inv + b * NN + z * 128;
    float4 s = make_float4(0.f, 0.f, 0.f, 0.f);
    for (int r = 0; r < 128; r++) {
        float iv = ivp[r];
        float4 v = reinterpret_cast<const float4*>(sc + (size_t)r * NN)[c4];
        s.x += v.x * iv; s.y += v.y * iv; s.z += v.z * iv; s.w += v.w * iv;
    }
    reinterpret_cast<float4*>(g_colpart + ((size_t)z * BATCH + b) * NN)[c4] = s;
}

// ---------------- Kernel 3b: reduce partials --------------------------------
__global__ __launch_bounds__(256) void colsum_reduce_kernel()
{
    int i = blockIdx.x * 256 + threadIdx.x;            // 0 .. BATCH*NN-1
    int b = i >> 11, c = i & (NN - 1);
    float s = 0.f;
    for (int z = 0; z < CSPLIT; z++)
        s += g_colpart[((size_t)z * BATCH + b) * NN + c];
    g_colsum[i] = s;
}

// ---------------- Kernel 4: greedy one-to-one matching (1024 threads) -------
static constexpr int MBLK = 1024;
__global__ __launch_bounds__(MBLK) void match_kernel()
{
    int b = blockIdx.x;
    int tid = threadIdx.x;
    __shared__ float rVal[NN];
    __shared__ int   rArg[NN];
    __shared__ unsigned char colDead[NN];
    __shared__ float redV[MBLK];
    __shared__ int   redI[MBLK];
    __shared__ int   list[256];
    __shared__ int   listCnt;
    __shared__ int   selC;

    for (int i = tid; i < NN; i += MBLK) {
        rVal[i] = g_rowVal[b * NN + i];
        rArg[i] = g_rowArg[b * NN + i];
        colDead[i] = 0;
    }
    __syncthreads();

    const float* sc = g_scores + (size_t)b * NN * NN;   // E values

    for (int it = 0; it < NSAMP; it++) {
        float bv = -1.f; int br = 0;
        for (int r = tid; r < NN; r += MBLK) {
            float v = rVal[r];
            if (v > bv) { bv = v; br = r; }
        }
        redV[tid] = bv; redI[tid] = br; __syncthreads();
        for (int s = MBLK / 2; s > 0; s >>= 1) {
            if (tid < s) {
                float v2 = redV[tid + s]; int r2 = redI[tid + s];
                if (v2 > redV[tid] || (v2 == redV[tid] && r2 < redI[tid])) {
                    redV[tid] = v2; redI[tid] = r2;
                }
            }
            __syncthreads();
        }
        if (tid == 0) {
            int r = redI[0];
            int c = rArg[r];
            g_matchR[b * NSAMP + it] = r;
            g_matchC[b * NSAMP + it] = c;
            rVal[r] = -1.f;
            colDead[c] = 1;
            selC = c;
            listCnt = 0;
        }
        __syncthreads();

        int c = selC;
        for (int r = tid; r < NN; r += MBLK) {
            if (rVal[r] >= 0.f && rArg[r] == c) {
                int pos = atomicAdd(&listCnt, 1);
                if (pos < 256) list[pos] = r;
            }
        }
        __syncthreads();
        int cnt = listCnt; if (cnt > 256) cnt = 256;
        for (int li = 0; li < cnt; li++) {
            int r = list[li];
            const float* rowp = sc + (size_t)r * NN;
            float mv = -1.f; int mc = 0;
            for (int cc = tid; cc < NN; cc += MBLK) {
                if (!colDead[cc]) {
                    float v = rowp[cc];                 // raw E: same order in-row
                    if (v > mv) { mv = v; mc = cc; }
                }
            }
            redV[tid] = mv; redI[tid] = mc; __syncthreads();
            for (int s = MBLK / 2; s > 0; s >>= 1) {
                if (tid < s) {
                    float v2 = redV[tid + s]; int c2 = redI[tid + s];
                    if (v2 > redV[tid] || (v2 == redV[tid] && c2 < redI[tid])) {
                        redV[tid] = v2; redI[tid] = c2;
                    }
                }
                __syncthreads();
            }
            if (tid == 0) {
                rVal[r] = redV[0] * g_inv[b * NN + r];  // back to score units
                rArg[r] = redI[0];
            }
            __syncthreads();
        }
        __syncthreads();
    }
}

// ---------------- Kernel 5: gather + centroids + 3x3 Kabsch SVD + output ----
__global__ __launch_bounds__(128) void finalize_kernel(
    const float* __restrict__ src, const float* __restrict__ tgt,
    float* __restrict__ out, int out_size)
{
    int b = blockIdx.x, tid = threadIdx.x;
    __shared__ float rx[128], ry[128], rz[128];
    __shared__ float srcMean[3], corrMean[3];
    __shared__ float sp[NSAMP][3], tp[NSAMP][3];

    const float* sb = src + (size_t)b * NN * 3;
    const float* tb = tgt + (size_t)b * NN * 3;

    float sx = 0, sy = 0, sz = 0;
    for (int n = tid; n < NN; n += 128) {
        sx += sb[3 * n]; sy += sb[3 * n + 1]; sz += sb[3 * n + 2];
    }
    rx[tid] = sx; ry[tid] = sy; rz[tid] = sz; __syncthreads();
    for (int s = 64; s > 0; s >>= 1) {
        if (tid < s) { rx[tid] += rx[tid + s]; ry[tid] += ry[tid + s]; rz[tid] += rz[tid + s]; }
        __syncthreads();
    }
    if (tid == 0) {
        srcMean[0] = rx[0] / NN; srcMean[1] = ry[0] / NN; srcMean[2] = rz[0] / NN;
    }
    __syncthreads();

    sx = sy = sz = 0;
    for (int n = tid; n < NN; n += 128) {
        float w = g_colsum[b * NN + n];
        sx += tb[3 * n] * w; sy += tb[3 * n + 1] * w; sz += tb[3 * n + 2] * w;
    }
    rx[tid] = sx; ry[tid] = sy; rz[tid] = sz; __syncthreads();
    for (int s = 64; s > 0; s >>= 1) {
        if (tid < s) { rx[tid] += rx[tid + s]; ry[tid] += ry[tid + s]; rz[tid] += rz[tid + s]; }
        __syncthreads();
    }
    if (tid == 0) {
        corrMean[0] = rx[0] / NN; corrMean[1] = ry[0] / NN; corrMean[2] = rz[0] / NN;
    }

    if (tid < NSAMP) {
        int r = g_matchR[b * NSAMP + tid];
        int c = g_matchC[b * NSAMP + tid];
        sp[tid][0] = sb[3 * r]; sp[tid][1] = sb[3 * r + 1]; sp[tid][2] = sb[3 * r + 2];
        tp[tid][0] = tb[3 * c]; tp[tid][1] = tb[3 * c + 1]; tp[tid][2] = tb[3 * c + 2];
    }
    __syncthreads();

    if (tid == 0) {
        double ms[3] = {0, 0, 0}, mt[3] = {0, 0, 0};
        for (int s = 0; s < NSAMP; s++)
            for (int i = 0; i < 3; i++) { ms[i] += sp[s][i]; mt[i] += tp[s][i]; }
        for (int i = 0; i < 3; i++) { ms[i] /= NSAMP; mt[i] /= NSAMP; }

        double H[3][3] = {};
        for (int s = 0; s < NSAMP; s++)
            for (int i = 0; i < 3; i++)
                for (int j = 0; j < 3; j++)
                    H[i][j] += ((double)sp[s][i] - ms[i]) * ((double)tp[s][j] - mt[j]);

        double Sm[3][3];
        for (int i = 0; i < 3; i++)
            for (int j = 0; j < 3; j++) {
                double acc = 0;
                for (int k = 0; k < 3; k++) acc += H[k][i] * H[k][j];
                Sm[i][j] = acc;
            }
        double V[3][3] = {{1, 0, 0}, {0, 1, 0}, {0, 0, 1}};
        for (int sweep = 0; sweep < 12; sweep++) {
            for (int pi = 0; pi < 3; pi++) {
                for (int qi = pi + 1; qi < 3; qi++) {
                    double apq = Sm[pi][qi];
                    if (fabs(apq) < 1e-30) continue;
                    double app = Sm[pi][pi], aqq = Sm[qi][qi];
                    double theta = 0.5 * (aqq - app) / apq;
                    double tJ = ((theta >= 0) ? 1.0 : -1.0) /
                                (fabs(theta) + sqrt(theta * theta + 1.0));
                    double cJ = 1.0 / sqrt(tJ * tJ + 1.0);
                    double sJ = tJ * cJ;
                    for (int k = 0; k < 3; k++) {
                        double skp = Sm[k][pi], skq = Sm[k][qi];
                        Sm[k][pi] = cJ * skp - sJ * skq;
                        Sm[k][qi] = sJ * skp + cJ * skq;
                    }
                    for (int k = 0; k < 3; k++) {
                        double spk = Sm[pi][k], sqk = Sm[qi][k];
                        Sm[pi][k] = cJ * spk - sJ * sqk;
                        Sm[qi][k] = sJ * spk + cJ * sqk;
                    }
                    for (int k = 0; k < 3; k++) {
                        double vkp = V[k][pi], vkq = V[k][qi];
                        V[k][pi] = cJ * vkp - sJ * vkq;
                        V[k][qi] = sJ * vkp + cJ * vkq;
                    }
                }
            }
        }
        double lam[3] = {Sm[0][0], Sm[1][1], Sm[2][2]};
        int idx[3] = {0, 1, 2};
        for (int i = 0; i < 2; i++)
            for (int j = i + 1; j < 3; j++)
                if (lam[idx[j]] > lam[idx[i]]) { int t2 = idx[i]; idx[i] = idx[j]; idx[j] = t2; }
        double Vc[3][3], U[3][3];
        for (int k = 0; k < 3; k++) {
            int c = idx[k];
            double sig = sqrt(lam[c] > 0 ? lam[c] : 0);
            double invs = (sig > 1e-300) ? 1.0 / sig : 0.0;
            for (int i = 0; i < 3; i++) Vc[i][k] = V[i][c];
            for (int i = 0; i < 3; i++) {
                double acc = 0;
                for (int j = 0; j < 3; j++) acc += H[i][j] * Vc[j][k];
                U[i][k] = acc * invs;
            }
        }
        double R[3][3];
        for (int i = 0; i < 3; i++)
            for (int j = 0; j < 3; j++) {
                double acc = 0;
                for (int k = 0; k < 3; k++) acc += Vc[i][k] * U[j][k];
                R[i][j] = acc;
            }
        double det =
            R[0][0] * (R[1][1] * R[2][2] - R[1][2] * R[2][1]) -
            R[0][1] * (R[1][0] * R[2][2] - R[1][2] * R[2][0]) +
            R[0][2] * (R[1][0] * R[2][1] - R[1][1] * R[2][0]);
        if (det < 0) {
            for (int i = 0; i < 3; i++)
                for (int j = 0; j < 3; j++)
                    R[i][j] -= 2.0 * Vc[i][2] * U[j][2];
        }
        double tv[3];
        for (int i = 0; i < 3; i++) {
            double acc = 0;
            for (int j = 0; j < 3; j++) acc += R[i][j] * (double)srcMean[j];
            tv[i] = -acc + (double)corrMean[i];
        }
        for (int i = 0; i < 3; i++)
            for (int j = 0; j < 3; j++)
                out[b * 9 + i * 3 + j] = (float)R[i][j];
        if (out_size >= BATCH * 9 + BATCH * 3) {
            for (int i = 0; i < 3; i++)
                out[BATCH * 9 + b * 3 + i] = (float)tv[i];
        }
    }
}

// ---------------- launch ----------------
extern "C" void kernel_launch(void* const* d_in, const int* in_sizes, int n_in,
                              void* d_out, int out_size)
{
    const float* src_emb = (const float*)d_in[0];
    const float* tgt_emb = (const float*)d_in[1];
    const float* src     = (const float*)d_in[2];
    const float* tgt     = (const float*)d_in[3];
    float* out = (float*)d_out;

    cudaFuncSetAttribute(gemm_hmma_kernel,
                         cudaFuncAttributeMaxDynamicSharedMemorySize, SM_GEMM_TOTAL);

    __nv_bfloat16 *pAh, *pAl, *pBh, *pBl;
    cudaGetSymbolAddress((void**)&pAh, g_Ah);
    cudaGetSymbolAddress((void**)&pAl, g_Al);
    cudaGetSymbolAddress((void**)&pBh, g_Bh);
    cudaGetSymbolAddress((void**)&pBl, g_Bl);

    dim3 gConv(NN / 32, DIMD / 32, 2 * BATCH);
    convert_kernel<<<gConv, 256>>>(src_emb, tgt_emb, pAh, pAl, pBh, pBl);

    dim3 gGemm(NN / 128, NN / 128, BATCH);
    gemm_hmma_kernel<<<gGemm, 256, SM_GEMM_TOTAL>>>();

    stats_reduce_kernel<<<(BATCH * NN) / 256, 256>>>();

    dim3 gColP(2, BATCH, CSPLIT);
    colsum_part_kernel<<<gColP, 256>>>();
    colsum_reduce_kernel<<<(BATCH * NN) / 256, 256>>>();

    match_kernel<<<BATCH, MBLK>>>();

    finalize_kernel<<<BATCH, 128>>>(src, tgt, out, out_size);
}